// round 3
// baseline (speedup 1.0000x reference)
#include <cuda_runtime.h>

// LightConv depthwise causal conv, GB300 sm_103a.
// x: [T=4096, B=8, C=1024] fp32, weight: [H=16, K=31] fp32 (softmax over K per head).
// out[t, b, c] = sum_{k=0..30} softmax(w)[c/64, k] * x[t-30+k, b, c]   (x=0 for t<0)
//
// Strategy: each thread owns one float2 column (2 adjacent channels, same head),
// streams along t with a 31-slot rolling accumulator ring held in registers.
// Each loaded x[s] issues 31 packed fma.rn.f32x2 (FFMA2) into 31 future outputs:
//   tap w[0]  -> MUL-init of slot for out[s+30]
//   taps w[1..29] -> FMA into intermediate slots
//   tap w[30] -> drain: out[s] = acc + w[30]*x[s], store
// Unrolled in blocks of 31 steps so ring indices are compile-time constants.
// Loads for each 31-step block are batched first (xb[31]) for high MLP.

#define T_DIM   4096
#define B_DIM   8
#define C_DIM   1024
#define H_DIM   16
#define K_TAPS  31
#define BC2     ((B_DIM * C_DIM) / 2)   // 4096 float2 columns
#define ROW_U64 ((B_DIM * C_DIM) / 2)   // u64 elements per t-row = 4096
#define TT      248                     // outputs per t-tile per thread (8*31)
#define NBLK_J  (TT / K_TAPS)           // 8 main blocks
#define THREADS 128

typedef unsigned long long u64;

__device__ float g_w[H_DIM * K_TAPS];

// ---------------------------------------------------------------------------
// Tiny softmax preprocessing kernel: g_w[h][k] = softmax(weight[h, :])[k]
// ---------------------------------------------------------------------------
__global__ void lc_softmax_kernel(const float* __restrict__ w) {
    int h = threadIdx.x;
    if (h >= H_DIM) return;
    float v[K_TAPS];
    float m = -1e30f;
#pragma unroll
    for (int k = 0; k < K_TAPS; k++) {
        v[k] = w[h * K_TAPS + k];
        m = fmaxf(m, v[k]);
    }
    float s = 0.0f;
#pragma unroll
    for (int k = 0; k < K_TAPS; k++) {
        v[k] = expf(v[k] - m);
        s += v[k];
    }
    float inv = 1.0f / s;
#pragma unroll
    for (int k = 0; k < K_TAPS; k++) {
        g_w[h * K_TAPS + k] = v[k] * inv;
    }
}

// ---------------------------------------------------------------------------
// Packed f32x2 helpers (Blackwell-only PTX; maps to FFMA2/FMUL2 in SASS)
// ---------------------------------------------------------------------------
__device__ __forceinline__ u64 ffma2(u64 a, u64 b, u64 c) {
    u64 d;
    asm("fma.rn.f32x2 %0, %1, %2, %3;" : "=l"(d) : "l"(a), "l"(b), "l"(c));
    return d;
}
__device__ __forceinline__ u64 fmul2(u64 a, u64 b) {
    u64 d;
    asm("mul.rn.f32x2 %0, %1, %2;" : "=l"(d) : "l"(a), "l"(b));
    return d;
}

// ---------------------------------------------------------------------------
// Main kernel
// grid.x: bc2 tiles (4096 / 128 = 32), grid.y: t tiles (ceil(4096/248) = 17)
// ---------------------------------------------------------------------------
__global__ __launch_bounds__(THREADS) void lightconv_kernel(
    const float* __restrict__ x, float* __restrict__ out)
{
    const int bc2 = blockIdx.x * THREADS + threadIdx.x;   // float2 column index
    const int t0  = blockIdx.y * TT;                       // tile origin, t0 % 31 == 0
    const int c   = (bc2 * 2) & (C_DIM - 1);
    const int h   = c >> 6;                                // 64 channels per head

    // Load this head's 31 softmaxed taps, packed {w, w} for f32x2.
    u64 wv[K_TAPS];
#pragma unroll
    for (int k = 0; k < K_TAPS; k++) {
        unsigned int b = __float_as_uint(g_w[h * K_TAPS + k]);
        wv[k] = ((u64)b << 32) | (u64)b;
    }

    const u64* __restrict__ px = (const u64*)x + bc2;
    u64* __restrict__ po       = (u64*)out + bc2;

    const long s_base = (long)t0 - K_TAPS;   // first step; s_base % 31 == 0

    u64 acc[K_TAPS];
#pragma unroll
    for (int u = 0; u < K_TAPS; u++) acc[u] = 0ull;

    u64 xb[K_TAPS];

    // ---- prologue block (j = 0): steps s_base .. s_base+30, NO stores ----
    {
        const u64* p0 = px + s_base * ROW_U64;
#pragma unroll
        for (int u = 0; u < K_TAPS; u++) {
            long s = s_base + u;
            xb[u] = (s >= 0) ? p0[(long)u * ROW_U64] : 0ull;
        }
#pragma unroll
        for (int u = 0; u < K_TAPS; u++) {
            u64 xv = xb[u];
            // drain of slot u suppressed (output < t0); slot re-inited next step
#pragma unroll
            for (int d = 1; d <= 29; d++) {
                acc[(u + d) % K_TAPS] = ffma2(wv[30 - d], xv, acc[(u + d) % K_TAPS]);
            }
            acc[(u + 30) % K_TAPS] = fmul2(wv[0], xv);   // init out[s+30] with tap w[0]
        }
    }

    // ---- main blocks j = 1..8: steps t0+(j-1)*31 .. t0+j*31-1, stores on ----
#pragma unroll 1
    for (int j = 1; j <= NBLK_J; j++) {
        const long sj = s_base + (long)j * K_TAPS;        // = t0 + (j-1)*31
        const u64* __restrict__ pj = px + sj * ROW_U64;
        u64* __restrict__ qj       = po + sj * ROW_U64;

        // batched loads for the whole block (MLP burst)
#pragma unroll
        for (int u = 0; u < K_TAPS; u++) {
            xb[u] = (sj + u < T_DIM) ? pj[(long)u * ROW_U64] : 0ull;
        }

#pragma unroll
        for (int u = 0; u < K_TAPS; u++) {
            u64 xv = xb[u];
            // drain: out[s] = acc + w[30] * x[s]
            u64 o = ffma2(wv[30], xv, acc[u]);
            if (sj + u < T_DIM) {
                qj[(long)u * ROW_U64] = o;
            }
            // middle taps
#pragma unroll
            for (int d = 1; d <= 29; d++) {
                acc[(u + d) % K_TAPS] = ffma2(wv[30 - d], xv, acc[(u + d) % K_TAPS]);
            }
            // first tap initializes the freshly-freed slot (no zeroing needed)
            acc[(u + 30) % K_TAPS] = fmul2(wv[0], xv);
        }
    }
}

// ---------------------------------------------------------------------------
// Launch
// ---------------------------------------------------------------------------
extern "C" void kernel_launch(void* const* d_in, const int* in_sizes, int n_in,
                              void* d_out, int out_size) {
    const float* x = (const float*)d_in[0];
    const float* w = (const float*)d_in[1];
    // robustness: x is the big tensor
    if (n_in >= 2 && in_sizes[0] < in_sizes[1]) {
        x = (const float*)d_in[1];
        w = (const float*)d_in[0];
    }

    lc_softmax_kernel<<<1, 32>>>(w);

    dim3 grid(BC2 / THREADS, (T_DIM + TT - 1) / TT);   // (32, 17)
    lightconv_kernel<<<grid, THREADS>>>(x, (float*)d_out);
}

// round 4
// speedup vs baseline: 1.1670x; 1.1670x over previous
#include <cuda_runtime.h>

// LightConv depthwise causal conv, GB300 sm_103a.
// x: [T=4096, B=8, C=1024] fp32, weight: [H=16, K=31] fp32 (softmax over K per head).
// out[t,b,c] = sum_{k=0..30} softmax(w)[c/64, k] * x[t-30+k, b, c]   (x = 0 for t < 0)
//
// Each thread owns one float2 column (2 adjacent channels, same head) and streams
// along t with a 31-slot rolling accumulator ring in registers. Every loaded x[s]
// scatters 31 packed fma.rn.f32x2 into 31 future outputs:
//   tap w[30] -> drain: out[s] = acc + w[30]*x[s]  (store)
//   taps w[29..1] -> FMA into intermediate slots
//   tap w[0]  -> MUL-init of the freshly-drained slot (out[s+30])
// 31-step blocks keep ring indices compile-time. Loads are software-pipelined with
// a 31-step prefetch distance: step u refills xb[u] with the NEXT block's value
// right after consuming it, so every load has ~2000 cycles of FFMA2 cover.
// __launch_bounds__(128,2) gives ptxas 255 regs (~200 live) -> no spills.

#define T_DIM   4096
#define B_DIM   8
#define C_DIM   1024
#define H_DIM   16
#define K_TAPS  31
#define ROW     ((B_DIM * C_DIM) / 2)   // u64 elements per t-row = 4096
#define BC2     ((B_DIM * C_DIM) / 2)   // float2 columns = 4096
#define NJ      15                      // 31-step blocks per tile
#define TT      (NJ * K_TAPS)           // 465 outputs per tile
#define GRIDY   ((T_DIM + TT - 1) / TT) // 9
#define THREADS 128

typedef unsigned long long u64;

__device__ __forceinline__ u64 ffma2(u64 a, u64 b, u64 c) {
    u64 d;
    asm("fma.rn.f32x2 %0, %1, %2, %3;" : "=l"(d) : "l"(a), "l"(b), "l"(c));
    return d;
}
__device__ __forceinline__ u64 fmul2(u64 a, u64 b) {
    u64 d;
    asm("mul.rn.f32x2 %0, %1, %2;" : "=l"(d) : "l"(a), "l"(b));
    return d;
}

__global__ __launch_bounds__(THREADS, 2) void lightconv_kernel(
    const float* __restrict__ x, const float* __restrict__ wg,
    float* __restrict__ out)
{
    const int bc2 = blockIdx.x * THREADS + threadIdx.x;   // float2 column
    const int t0  = blockIdx.y * TT;                       // t0 % 31 == 0
    const int h   = ((bc2 * 2) & (C_DIM - 1)) >> 6;        // 64 channels per head

    // ---- inline per-thread softmax of this head's 31 taps ----
    float wf[K_TAPS];
    float mx = -3.402823466e38f;
#pragma unroll
    for (int k = 0; k < K_TAPS; k++) {
        wf[k] = __ldg(wg + h * K_TAPS + k);
        mx = fmaxf(mx, wf[k]);
    }
    float ssum = 0.0f;
#pragma unroll
    for (int k = 0; k < K_TAPS; k++) {
        wf[k] = expf(wf[k] - mx);
        ssum += wf[k];
    }
    const float inv = 1.0f / ssum;
    u64 wv[K_TAPS];                                        // {w,w} packed for f32x2
#pragma unroll
    for (int k = 0; k < K_TAPS; k++) {
        unsigned int b = __float_as_uint(wf[k] * inv);
        wv[k] = ((u64)b << 32) | (u64)b;
    }

    const u64* __restrict__ px = (const u64*)x + bc2;
    u64* __restrict__ po       = (u64*)out + bc2;
    const int sb = t0 - K_TAPS;                            // first step; sb % 31 == 0

    u64 acc[K_TAPS];
    u64 xb[K_TAPS];
#pragma unroll
    for (int u = 0; u < K_TAPS; u++) acc[u] = 0ull;

    // ---- upfront loads for block j=0 (steps sb .. sb+30) ----
    {
        const u64* p0 = px + (long)sb * ROW;
#pragma unroll
        for (int u = 0; u < K_TAPS; u++) {
            xb[u] = (sb + u >= 0) ? p0[(long)u * ROW] : 0ull;
        }
    }

    // ---- unified loop: j=0 is the warm-up block (stores off), j=1..NJ store ----
#pragma unroll 1
    for (int j = 0; j <= NJ; j++) {
        const int sj = sb + j * K_TAPS;
        if (sj >= T_DIM) break;                            // fully-OOB tail blocks
        const u64* __restrict__ pf = px + (long)(sj + K_TAPS) * ROW;  // prefetch base
        u64* __restrict__ q        = po + (long)sj * ROW;
        const bool pfon = (j < NJ);
        const bool ston = (j > 0);

#pragma unroll
        for (int u = 0; u < K_TAPS; u++) {
            u64 xv = xb[u];
            // prefetch NEXT block's value into the just-freed slot (31-step distance)
            if (pfon && (sj + K_TAPS + u) < T_DIM) {
                xb[u] = pf[(long)u * ROW];
            }
            // drain: out[sj+u] = acc + w[30]*x  (discarded in warm-up block)
            u64 o = ffma2(wv[30], xv, acc[u]);
            if (ston && (sj + u) < T_DIM) {
                q[(long)u * ROW] = o;
            }
            // middle taps scatter into the ring (compile-time indices)
#pragma unroll
            for (int d = 1; d <= 29; d++) {
                acc[(u + d) % K_TAPS] = ffma2(wv[30 - d], xv, acc[(u + d) % K_TAPS]);
            }
            // first tap re-initializes the drained slot (no zeroing needed)
            acc[(u + 30) % K_TAPS] = fmul2(wv[0], xv);
        }
    }
}

extern "C" void kernel_launch(void* const* d_in, const int* in_sizes, int n_in,
                              void* d_out, int out_size) {
    const float* x = (const float*)d_in[0];
    const float* w = (const float*)d_in[1];
    if (n_in >= 2 && in_sizes[0] < in_sizes[1]) {   // robustness: x is the big tensor
        x = (const float*)d_in[1];
        w = (const float*)d_in[0];
    }
    dim3 grid(BC2 / THREADS, GRIDY);                // (32, 9) = 288 blocks, one wave
    lightconv_kernel<<<grid, THREADS>>>(x, w, (float*)d_out);
}

// round 10
// speedup vs baseline: 1.2144x; 1.0406x over previous
#include <cuda_runtime.h>

// LightConv depthwise causal conv, GB300 sm_103a — pure register pipeline.
// x: [T=4096, B=8, C=1024] fp32, weight: [H=16, K=31] fp32 (softmax over K per head).
// out[t,b,c] = sum_k softmax(w)[c/64,k] * x[t-30+k, b, c]   (x = 0 for t < 0)
//
// Register rolling-accumulator ring (proven R3 architecture), occupancy-3:
//  - 32-slot accumulator ring ("&31" indexing): slot for out[g] is g&31,
//    initialized (tap w[0]) 30 steps early, drained (tap w[30]) at step g,
//    taps w[29..1] scattered in between; 2-step dead window per slot.
//  - 8-slot prefetch ring xb[8]; 32 % 8 == 0 keeps indices compile-time.
//    Distance 8 steps (~744 cyc of FFMA2 at 3 warps/SMSP) covers DRAM latency.
//  - regs ~164 -> __launch_bounds__(128,3): 3 blocks/SM = 12 warps/SM.
// Tiling: TT=320 (warm-up stage + 10 store stages of 32 rows), grid (32,13)
// = 416 blocks ~ one wave. Last tile clamped to t0=3776 (duplicate stores
// write identical values; both t0 values are %32==0 so slot==u holds).
//
// R9 fix vs R8: prefetch was disabled for the WHOLE last stage, but with
// PF(8) < stage(32), steps u>=8 of the last stage consume in-stage refills
// -> last 24 rows of every tile were computed from stale x (rel_err 0.28 =
// sqrt(24/320), confirmed). Now the last stage keeps refills for u < 24
// (in-bounds, in-stage) and drops only the 8 dead next-stage refills.

#define T_DIM   4096
#define B_DIM   8
#define C_DIM   1024
#define K_TAPS  31
#define SLOTS   32                        // accumulator ring size (power of 2)
#define PF      8                         // prefetch ring size, divides SLOTS
#define ROW     ((B_DIM * C_DIM) / 2)     // u64 per t-row = 4096
#define BC2     ((B_DIM * C_DIM) / 2)
#define THREADS 128
#define NJ      10                        // store stages per tile
#define TT      (NJ * SLOTS)              // 320 outputs per tile
#define GRIDY   13                        // 12*320=3840 < 4096, last tile clamped
#define NSTAGES (NJ + 1)                  // + warm-up stage

typedef unsigned long long u64;
typedef unsigned int u32;

__device__ __forceinline__ u64 ffma2(u64 a, u64 b, u64 c) {
    u64 d;
    asm("fma.rn.f32x2 %0, %1, %2, %3;" : "=l"(d) : "l"(a), "l"(b), "l"(c));
    return d;
}
__device__ __forceinline__ u64 fmul2(u64 a, u64 b) {
    u64 d;
    asm("mul.rn.f32x2 %0, %1, %2;" : "=l"(d) : "l"(a), "l"(b));
    return d;
}

__global__ __launch_bounds__(THREADS, 3) void lightconv_kernel(
    const float* __restrict__ x, const float* __restrict__ wg,
    float* __restrict__ out)
{
    const int tid = threadIdx.x;
    const int bc2 = blockIdx.x * THREADS + tid;            // this thread's u64 column
    const int by  = blockIdx.y;
    const int t0  = (by < GRIDY - 1) ? by * TT : (T_DIM - TT);  // 3776 % 32 == 0
    const int h   = ((bc2 * 2) & (C_DIM - 1)) >> 6;        // head (warp-uniform)

    // ---- per-thread softmax of this head's 31 taps, packed {w,w} ----
    float wf[K_TAPS];
    float mx = -3.402823466e38f;
#pragma unroll
    for (int k = 0; k < K_TAPS; k++) {
        wf[k] = __ldg(wg + h * K_TAPS + k);
        mx = fmaxf(mx, wf[k]);
    }
    float ssum = 0.0f;
#pragma unroll
    for (int k = 0; k < K_TAPS; k++) { wf[k] = expf(wf[k] - mx); ssum += wf[k]; }
    const float inv = 1.0f / ssum;
    u64 wv[K_TAPS];
#pragma unroll
    for (int k = 0; k < K_TAPS; k++) {
        u32 b = __float_as_uint(wf[k] * inv);
        wv[k] = ((u64)b << 32) | (u64)b;
    }

    const u64* __restrict__ px = (const u64*)x + bc2;      // per-thread column
    u64* __restrict__ po       = (u64*)out + bc2;

    const int s0 = t0 - SLOTS;                             // first warm-up row

    u64 acc[SLOTS];
#pragma unroll
    for (int u = 0; u < SLOTS; u++) acc[u] = 0ull;

    // ---- initial prefetch: rows s0 .. s0+7 (zeros for t<0, tile 0 only) ----
    u64 xb[PF];
#pragma unroll
    for (int p = 0; p < PF; p++) {
        const int tr = s0 + p;
        xb[p] = (tr >= 0) ? px[(long)tr * ROW] : 0ull;
    }

    // ---- stages: j=0 warm-up (no stores), j=1..NJ store 32 rows each ----
#pragma unroll 1
    for (int j = 0; j < NSTAGES; j++) {
        const int rowbase = s0 + j * SLOTS;                // row of step u=0
        const u64* __restrict__ pfp = px + (long)(rowbase + PF) * ROW;
        u64* __restrict__ q         = po + (long)rowbase * ROW;
        const bool ston = (j > 0);
        const bool pfon = (j + 1 < NSTAGES);               // next stage exists

#pragma unroll
        for (int u = 0; u < SLOTS; u++) {
            u64 xv = xb[u & (PF - 1)];
            // refill row rowbase+u+PF. In the last stage, refills at
            // u < SLOTS-PF feed THIS stage (rows < t0+TT <= T_DIM, in-bounds);
            // the final PF refills feed a nonexistent stage -> dropped.
            if (pfon || u < SLOTS - PF) {
                const int tr = rowbase + u + PF;
                xb[u & (PF - 1)] = (tr >= 0) ? pfp[(long)u * ROW] : 0ull;
            }
            // drain slot u: out[rowbase+u] = acc + w[30]*x[rowbase+u]
            u64 o = ffma2(wv[30], xv, acc[u]);
            if (ston) q[(long)u * ROW] = o;                // no bound check
            // scatter middle taps (all indices compile-time)
#pragma unroll
            for (int d = 1; d <= 29; d++) {
                acc[(u + d) & (SLOTS - 1)] =
                    ffma2(wv[30 - d], xv, acc[(u + d) & (SLOTS - 1)]);
            }
            // first tap initializes the slot for out[rowbase+u+30]
            acc[(u + 30) & (SLOTS - 1)] = fmul2(wv[0], xv);
        }
    }
}

extern "C" void kernel_launch(void* const* d_in, const int* in_sizes, int n_in,
                              void* d_out, int out_size) {
    const float* x = (const float*)d_in[0];
    const float* w = (const float*)d_in[1];
    if (n_in >= 2 && in_sizes[0] < in_sizes[1]) {   // robustness: x is the big tensor
        x = (const float*)d_in[1];
        w = (const float*)d_in[0];
    }
    dim3 grid(BC2 / THREADS, GRIDY);                // (32, 13) = 416 blocks, one wave
    lightconv_kernel<<<grid, THREADS>>>(x, w, (float*)d_out);
}